// round 11
// baseline (speedup 1.0000x reference)
#include <cuda_runtime.h>
#include <cstdint>

// GCN 2-layer: out = spmm(relu(spmm(X)@W1))@W2,  A_norm = D^-1/2 A D^-1/2
// N=50000, E=850000 (last N edges are self-loops, verified at runtime), D=64.
//
// R11 = R10 resubmission (R10 hit broker infra failure, never ran):
//   - scalar-FFMA GEMM with X staged in smem TRANSPOSED (Xs[k][r]): X read
//     from global exactly once; inner loop pure LDS+FFMA (no LDG stalls)
//   - 128 thr/CTA, 4 rows x 16 cols/thread, 3 CTAs/SM, smem 48KB
//
// Pipeline (correctness-proven in R9, rel_err 2.6e-7):
//   xs   = dis .* X ; agg1 = xs (loop term)     [fused prescale]
//   agg1 += scatter-add xs[src] over non-loop edges (red.global.add.v4.f32)
//   hs   = relu(dis .* (agg1@W1)) .* dis ; agg2 = hs   [gemm1 epilogue]
//   agg2 += scatter-add hs[src]
//   out  = dis .* (agg2@W2)

#define D 64
#define NMAX 50176

__device__ float g_xs[NMAX * D];    // prescaled features (xs, then hs)
__device__ float g_agg[NMAX * D];   // layer-1 aggregation
__device__ float g_agg2[NMAX * D];  // layer-2 aggregation
__device__ int g_is64;
__device__ int g_loops;             // 1 if last N edges are self-loops i->i
__device__ int g_E2;                // effective scatter edge count

// ---------------------------------------------------------------------------
// Detection: edge dtype (int64 vs int32) + "last N edges are self-loops".
// ---------------------------------------------------------------------------
__global__ void __launch_bounds__(1024) detect_kernel(const void* __restrict__ ei,
                                                      int E, int N) {
    __shared__ int s_is64;
    __shared__ int s_ok;
    int t = threadIdx.x;
    if (t == 0) {
        const int* w = (const int*)ei;
        int is64 = 1;
        #pragma unroll 1
        for (int i = 0; i < 64; i++)
            if (w[2 * i + 1] != 0) { is64 = 0; break; }
        s_is64 = is64;
        s_ok = (E >= N) ? 1 : 0;
    }
    __syncthreads();
    int is64 = s_is64;

    if (E >= N) {
        long long pos = (long long)t * N / 1024;
        long long eidx = (long long)(E - N) + pos;
        long long s, d;
        if (is64) {
            const long long* p = (const long long*)ei;
            s = p[eidx]; d = p[E + eidx];
        } else {
            const int* p = (const int*)ei;
            s = p[eidx]; d = p[E + eidx];
        }
        if (s != pos || d != pos) s_ok = 0;   // benign race, any writer wins
    }
    __syncthreads();
    if (t == 0) {
        g_is64 = is64;
        g_loops = s_ok;
        g_E2 = s_ok ? (E - N) : E;
    }
}

// ---------------------------------------------------------------------------
// Fused prescale + layer1 init:
//   xs[i,:]   = dis[i] * x[i,:]
//   agg1[i,:] = loops ? xs[i,:] : 0      (loop term, pre-dst-scale)
// ---------------------------------------------------------------------------
__global__ void __launch_bounds__(256) prescale_kernel(
    const float4* __restrict__ x, const float* __restrict__ dis,
    float4* __restrict__ xs, float4* __restrict__ agg, int n4)
{
    int i = blockIdx.x * 256 + threadIdx.x;
    if (i >= n4) return;
    float s = dis[i >> 4];
    float4 v = x[i];
    v.x *= s; v.y *= s; v.z *= s; v.w *= s;
    xs[i] = v;
    agg[i] = g_loops ? v : make_float4(0.f, 0.f, 0.f, 0.f);
}

// ---------------------------------------------------------------------------
// Scatter SPMM: out[dst] += feat[src]   (feat already src-scaled)
// 16 threads/edge, one float4 gather + one red.global.add.v4.f32 each.
// ---------------------------------------------------------------------------
__global__ void __launch_bounds__(256) scatter_kernel(
    const float4* __restrict__ feat,
    const void*   __restrict__ ei,
    float*        __restrict__ out,
    int E)
{
    int idx = blockIdx.x * 256 + threadIdx.x;
    int e = idx >> 4;
    if (e >= g_E2) return;
    int lane = idx & 15;

    int s, d;
    if (g_is64) {
        const long long* p = (const long long*)ei;
        s = (int)p[e];
        d = (int)p[E + e];
    } else {
        const int* p = (const int*)ei;
        s = p[e];
        d = p[E + e];
    }

    float4 v = feat[s * 16 + lane];
    float* o = out + d * 64 + lane * 4;

    asm volatile("red.global.add.v4.f32 [%0], {%1, %2, %3, %4};"
                 :: "l"(o), "f"(v.x), "f"(v.y), "f"(v.z), "f"(v.w)
                 : "memory");
}

// ---------------------------------------------------------------------------
// GEMM: t = dis[r] * (X[r,:] @ W),  W is 64x64.
//   mode 0: Y[r,:] = t
//   mode 1: h = relu(t)*dis[r];  Y[r,:] = h;  A2[r,:] = h (or 0 if !loops)
// 128 thr/CTA, 4 rows x 16 cols/thread. X staged in smem transposed
// (Xs[k][r]) so the inner loop is pure LDS+FFMA. 3 CTAs/SM.
// ---------------------------------------------------------------------------
__global__ void __launch_bounds__(128, 3) gemm64_kernel(
    const float* __restrict__ X,
    const float* __restrict__ W,
    const float* __restrict__ dis,
    float*       __restrict__ Y,
    float*       __restrict__ A2,
    int n, int mode)
{
    __shared__ float Ws[64 * 64];    // [k][col]
    __shared__ float Xs[64 * 128];   // [k][row]  (transposed tile)

    int t = threadIdx.x;
    int rbase = blockIdx.x * 128;

    #pragma unroll
    for (int i = t; i < 1024; i += 128)
        ((float4*)Ws)[i] = ((const float4*)W)[i];

    // Stage X transposed. thread = local row; conflict-free STS
    // (consecutive threads -> consecutive r within each k-plane).
    {
        int gr = rbase + t;
        const float4* X4 = (const float4*)X;
        #pragma unroll
        for (int k4 = 0; k4 < 16; k4++) {
            float4 v = (gr < n) ? X4[gr * 16 + k4]
                                : make_float4(0.f, 0.f, 0.f, 0.f);
            Xs[(k4 * 4 + 0) * 128 + t] = v.x;
            Xs[(k4 * 4 + 1) * 128 + t] = v.y;
            Xs[(k4 * 4 + 2) * 128 + t] = v.z;
            Xs[(k4 * 4 + 3) * 128 + t] = v.w;
        }
    }
    __syncthreads();

    int rg = t >> 2;                 // 0..31
    int cg = (t & 3) << 4;           // 0,16,32,48
    int r0l = rg << 2;               // local row base (16B-aligned in Xs rows)

    float acc[4][16] = {};

    #pragma unroll 4
    for (int k = 0; k < 64; k++) {
        // one LDS.128: x values of 4 consecutive rows at this k
        float4 xv = *(const float4*)&Xs[k * 128 + r0l];
        const float* wrow = &Ws[k * 64 + cg];
        float4 w0 = *(const float4*)(wrow + 0);
        float4 w1 = *(const float4*)(wrow + 4);
        float4 w2 = *(const float4*)(wrow + 8);
        float4 w3 = *(const float4*)(wrow + 12);
        float xr[4] = {xv.x, xv.y, xv.z, xv.w};
        #pragma unroll
        for (int i = 0; i < 4; i++) {
            float xs = xr[i];
            acc[i][0]  += xs * w0.x; acc[i][1]  += xs * w0.y;
            acc[i][2]  += xs * w0.z; acc[i][3]  += xs * w0.w;
            acc[i][4]  += xs * w1.x; acc[i][5]  += xs * w1.y;
            acc[i][6]  += xs * w1.z; acc[i][7]  += xs * w1.w;
            acc[i][8]  += xs * w2.x; acc[i][9]  += xs * w2.y;
            acc[i][10] += xs * w2.z; acc[i][11] += xs * w2.w;
            acc[i][12] += xs * w3.x; acc[i][13] += xs * w3.y;
            acc[i][14] += xs * w3.z; acc[i][15] += xs * w3.w;
        }
    }

    int loops = (mode == 1) ? g_loops : 0;

    #pragma unroll
    for (int i = 0; i < 4; i++) {
        int r = rbase + r0l + i;
        if (r >= n) continue;
        float s = dis[r];
        float* yo = &Y[r * 64 + cg];
        if (mode == 0) {
            #pragma unroll
            for (int j4 = 0; j4 < 4; j4++) {
                float4 o;
                o.x = acc[i][j4 * 4 + 0] * s;
                o.y = acc[i][j4 * 4 + 1] * s;
                o.z = acc[i][j4 * 4 + 2] * s;
                o.w = acc[i][j4 * 4 + 3] * s;
                *(float4*)(yo + j4 * 4) = o;
            }
        } else {
            float* ao = &A2[r * 64 + cg];
            #pragma unroll
            for (int j4 = 0; j4 < 4; j4++) {
                float4 h;
                h.x = fmaxf(acc[i][j4 * 4 + 0] * s, 0.f) * s;
                h.y = fmaxf(acc[i][j4 * 4 + 1] * s, 0.f) * s;
                h.z = fmaxf(acc[i][j4 * 4 + 2] * s, 0.f) * s;
                h.w = fmaxf(acc[i][j4 * 4 + 3] * s, 0.f) * s;
                *(float4*)(yo + j4 * 4) = h;
                float4 a;
                if (loops) { a = h; }
                else       { a.x = 0.f; a.y = 0.f; a.z = 0.f; a.w = 0.f; }
                *(float4*)(ao + j4 * 4) = a;
            }
        }
    }
}

// ---------------------------------------------------------------------------
// Launch
// ---------------------------------------------------------------------------
extern "C" void kernel_launch(void* const* d_in, const int* in_sizes, int n_in,
                              void* d_out, int out_size)
{
    const float* x   = (const float*)d_in[0];
    const void*  ei  = d_in[1];
    const float* dis = (const float*)d_in[2];
    const float* W1  = (const float*)d_in[n_in - 2];
    const float* W2  = (const float*)d_in[n_in - 1];

    int N = in_sizes[0] / D;
    int E = in_sizes[1] / 2;

    float* xs   = nullptr;
    float* agg  = nullptr;
    float* agg2 = nullptr;
    cudaGetSymbolAddress((void**)&xs,   g_xs);
    cudaGetSymbolAddress((void**)&agg,  g_agg);
    cudaGetSymbolAddress((void**)&agg2, g_agg2);

    int n4    = N * (D / 4);
    int pgrid = (n4 + 255) / 256;
    int sgrid = (E * 16 + 255) / 256;   // sized for full E; extra threads exit
    int mgrid = (N + 127) / 128;

    detect_kernel<<<1, 1024>>>(ei, E, N);

    // Layer 1
    prescale_kernel<<<pgrid, 256>>>((const float4*)x, dis,
                                    (float4*)xs, (float4*)agg, n4);
    scatter_kernel<<<sgrid, 256>>>((const float4*)xs, ei, agg, E);
    gemm64_kernel<<<mgrid, 128>>>(agg, W1, dis, xs, agg2, N, 1);  // xs := hs

    // Layer 2
    scatter_kernel<<<sgrid, 256>>>((const float4*)xs, ei, agg2, E);
    gemm64_kernel<<<mgrid, 128>>>(agg2, W2, dis, (float*)d_out, nullptr, N, 0);
}

// round 12
// speedup vs baseline: 1.2245x; 1.2245x over previous
#include <cuda_runtime.h>
#include <cuda_fp16.h>
#include <cstdint>

// GCN 2-layer: out = spmm(relu(spmm(X)@W1))@W2,  A_norm = D^-1/2 A D^-1/2
// N=50000, E=850000 (last N edges self-loops, runtime-verified), D=64.
//
// R12: GEMM moved to tensor cores (mma.sync.m16n8k16 f16f16f32). FFMA GEMMs
// plateaued at ~25-29us across 5 variants (scalar issue floor + occupancy);
// HMMA makes compute free and the kernel staging-bound (~6us predicted).
// fp16 input precision validated empirically in R6 (rel_err 1.47e-4 full-fp16).
//
// Pipeline (proven R9/R11, rel_err 2.6e-7 in fp32 form):
//   xs   = dis .* X ; agg1 = xs (self-loop term)     [fused prescale]
//   agg1 += scatter-add xs[src], non-loop edges      (red.global.add.v4.f32)
//   hs   = relu(dis .* (agg1@W1)) .* dis ; agg2 = hs [gemm1 epilogue]
//   agg2 += scatter-add hs[src]
//   out  = dis .* (agg2@W2)

#define D 64
#define NMAX 50176

__device__ float g_xs[NMAX * D];    // prescaled features (xs, then hs)
__device__ float g_agg[NMAX * D];   // layer-1 aggregation
__device__ float g_agg2[NMAX * D];  // layer-2 aggregation
__device__ int g_is64;
__device__ int g_loops;
__device__ int g_E2;

// ---------------------------------------------------------------------------
// helpers
// ---------------------------------------------------------------------------
__device__ __forceinline__ unsigned h2u(float a, float b) {
    __half2 h = __floats2half2_rn(a, b);
    union { __half2 h; unsigned u; } c;
    c.h = h;
    return c.u;
}
__device__ __forceinline__ void ldmatrix_x4(unsigned* r, unsigned addr) {
    asm volatile("ldmatrix.sync.aligned.m8n8.x4.shared.b16 {%0,%1,%2,%3}, [%4];"
                 : "=r"(r[0]), "=r"(r[1]), "=r"(r[2]), "=r"(r[3]) : "r"(addr));
}
__device__ __forceinline__ void ldmatrix_x4_t(unsigned* r, unsigned addr) {
    asm volatile("ldmatrix.sync.aligned.m8n8.x4.trans.shared.b16 {%0,%1,%2,%3}, [%4];"
                 : "=r"(r[0]), "=r"(r[1]), "=r"(r[2]), "=r"(r[3]) : "r"(addr));
}
__device__ __forceinline__ void mma16816(float* c, const unsigned* a,
                                         unsigned b0, unsigned b1) {
    asm volatile(
        "mma.sync.aligned.m16n8k16.row.col.f32.f16.f16.f32 "
        "{%0,%1,%2,%3}, {%4,%5,%6,%7}, {%8,%9}, {%0,%1,%2,%3};"
        : "+f"(c[0]), "+f"(c[1]), "+f"(c[2]), "+f"(c[3])
        : "r"(a[0]), "r"(a[1]), "r"(a[2]), "r"(a[3]), "r"(b0), "r"(b1));
}

// ---------------------------------------------------------------------------
// Detection: edge dtype + trailing-self-loop structure.
// ---------------------------------------------------------------------------
__global__ void __launch_bounds__(1024) detect_kernel(const void* __restrict__ ei,
                                                      int E, int N) {
    __shared__ int s_is64;
    __shared__ int s_ok;
    int t = threadIdx.x;
    if (t == 0) {
        const int* w = (const int*)ei;
        int is64 = 1;
        #pragma unroll 1
        for (int i = 0; i < 64; i++)
            if (w[2 * i + 1] != 0) { is64 = 0; break; }
        s_is64 = is64;
        s_ok = (E >= N) ? 1 : 0;
    }
    __syncthreads();
    int is64 = s_is64;
    if (E >= N) {
        long long pos = (long long)t * N / 1024;
        long long eidx = (long long)(E - N) + pos;
        long long s, d;
        if (is64) {
            const long long* p = (const long long*)ei;
            s = p[eidx]; d = p[E + eidx];
        } else {
            const int* p = (const int*)ei;
            s = p[eidx]; d = p[E + eidx];
        }
        if (s != pos || d != pos) s_ok = 0;
    }
    __syncthreads();
    if (t == 0) {
        g_is64 = is64;
        g_loops = s_ok;
        g_E2 = s_ok ? (E - N) : E;
    }
}

// ---------------------------------------------------------------------------
// Fused prescale + layer1 init
// ---------------------------------------------------------------------------
__global__ void __launch_bounds__(256) prescale_kernel(
    const float4* __restrict__ x, const float* __restrict__ dis,
    float4* __restrict__ xs, float4* __restrict__ agg, int n4)
{
    int i = blockIdx.x * 256 + threadIdx.x;
    if (i >= n4) return;
    float s = dis[i >> 4];
    float4 v = x[i];
    v.x *= s; v.y *= s; v.z *= s; v.w *= s;
    xs[i] = v;
    agg[i] = g_loops ? v : make_float4(0.f, 0.f, 0.f, 0.f);
}

// ---------------------------------------------------------------------------
// Scatter SPMM: out[dst] += feat[src]
// ---------------------------------------------------------------------------
__global__ void __launch_bounds__(256) scatter_kernel(
    const float4* __restrict__ feat,
    const void*   __restrict__ ei,
    float*        __restrict__ out,
    int E)
{
    int idx = blockIdx.x * 256 + threadIdx.x;
    int e = idx >> 4;
    if (e >= g_E2) return;
    int lane = idx & 15;

    int s, d;
    if (g_is64) {
        const long long* p = (const long long*)ei;
        s = (int)p[e];
        d = (int)p[E + e];
    } else {
        const int* p = (const int*)ei;
        s = p[e];
        d = p[E + e];
    }

    float4 v = feat[s * 16 + lane];
    float* o = out + d * 64 + lane * 4;

    asm volatile("red.global.add.v4.f32 [%0], {%1, %2, %3, %4};"
                 :: "l"(o), "f"(v.x), "f"(v.y), "f"(v.z), "f"(v.w)
                 : "memory");
}

// ---------------------------------------------------------------------------
// Tensor-core GEMM: t = dis[r] * (X[r,:] @ W),  W 64x64, X fp32 in gmem.
//   mode 0: Y = t ;  mode 1: h = relu(t)*dis[r]; Y = h; A2 = (loops ? h : 0)
// 256 thr (8 warps x 16 rows = 128 rows/CTA). X,W converted to fp16 in smem
// (128B-row XOR swizzle), ldmatrix fragments, mma.m16n8k16, fp32 accum.
// ---------------------------------------------------------------------------
__global__ void __launch_bounds__(256) gemm64_kernel(
    const float* __restrict__ X,
    const float* __restrict__ W,
    const float* __restrict__ dis,
    float*       __restrict__ Y,
    float*       __restrict__ A2,
    int n, int mode)
{
    __shared__ __align__(16) __half Wh[64 * 64];    // [k][n], 128B rows
    __shared__ __align__(16) __half Xh[128 * 64];   // [row][k], 128B rows

    int t = threadIdx.x;
    int rbase = blockIdx.x * 128;

    // ---- stage W (fp32 -> fp16, swizzled) ----
    {
        int row = t >> 2, q = t & 3;                // row 0..63, quarter 0..3
        const float4* W4 = (const float4*)W;
        float4 f0 = W4[row * 16 + q * 4 + 0];
        float4 f1 = W4[row * 16 + q * 4 + 1];
        float4 f2 = W4[row * 16 + q * 4 + 2];
        float4 f3 = W4[row * 16 + q * 4 + 3];
        uint4 u0, u1;
        u0.x = h2u(f0.x, f0.y); u0.y = h2u(f0.z, f0.w);
        u0.z = h2u(f1.x, f1.y); u0.w = h2u(f1.z, f1.w);
        u1.x = h2u(f2.x, f2.y); u1.y = h2u(f2.z, f2.w);
        u1.z = h2u(f3.x, f3.y); u1.w = h2u(f3.z, f3.w);
        unsigned sw = (row & 7) << 4;
        char* base = (char*)Wh;
        *(uint4*)(base + ((row * 128 + q * 32     ) ^ sw)) = u0;
        *(uint4*)(base + ((row * 128 + q * 32 + 16) ^ sw)) = u1;
    }

    // ---- stage X tile (fp32 -> fp16, swizzled) ----
    {
        int row = t >> 1, h = t & 1;                // row 0..127, half 0..1
        int gr = rbase + row;
        const float4* X4 = (const float4*)X;
        unsigned sw = (row & 7) << 4;
        char* base = (char*)Xh;
        #pragma unroll
        for (int c = 0; c < 4; c++) {
            float4 fa, fb;
            if (gr < n) {
                fa = X4[gr * 16 + h * 8 + c * 2 + 0];
                fb = X4[gr * 16 + h * 8 + c * 2 + 1];
            } else {
                fa = make_float4(0.f, 0.f, 0.f, 0.f);
                fb = fa;
            }
            uint4 u;
            u.x = h2u(fa.x, fa.y); u.y = h2u(fa.z, fa.w);
            u.z = h2u(fb.x, fb.y); u.w = h2u(fb.z, fb.w);
            *(uint4*)(base + ((row * 128 + (h * 4 + c) * 16) ^ sw)) = u;
        }
    }
    __syncthreads();

    int lane = t & 31, wid = t >> 5;
    int r0 = wid << 4;                              // warp's local row base

    unsigned xbase = (unsigned)__cvta_generic_to_shared(Xh);
    unsigned wbase = (unsigned)__cvta_generic_to_shared(Wh);

    // ---- A fragments: 4 k-chunks of 16 ----
    unsigned a[4][4];
    {
        int row = r0 + (lane & 7) + (lane & 8);
        unsigned sw = (row & 7) << 4;
        #pragma unroll
        for (int kk = 0; kk < 4; kk++) {
            int chunk = kk * 2 + (lane >> 4);
            unsigned addr = xbase + ((row * 128 + chunk * 16) ^ sw);
            ldmatrix_x4(a[kk], addr);
        }
    }

    float c[8][4];
    #pragma unroll
    for (int j = 0; j < 8; j++)
        #pragma unroll
        for (int q = 0; q < 4; q++)
            c[j][q] = 0.f;

    // ---- MMA main: 8 n-tiles x 4 k-steps ----
    #pragma unroll
    for (int j = 0; j < 8; j++) {
        unsigned b[8];
        {
            int k0 = lane;                          // rows 0..31
            unsigned addr0 = wbase + ((k0 * 128 + j * 16) ^ ((k0 & 7) << 4));
            ldmatrix_x4_t(b + 0, addr0);
            int k1 = 32 + lane;                     // rows 32..63
            unsigned addr1 = wbase + ((k1 * 128 + j * 16) ^ ((k1 & 7) << 4));
            ldmatrix_x4_t(b + 4, addr1);
        }
        mma16816(c[j], a[0], b[0], b[1]);
        mma16816(c[j], a[1], b[2], b[3]);
        mma16816(c[j], a[2], b[4], b[5]);
        mma16816(c[j], a[3], b[6], b[7]);
    }

    // ---- epilogue ----
    int loops = (mode == 1) ? g_loops : 0;
    int rA = rbase + r0 + (lane >> 2);
    int rB = rA + 8;
    int cb = (lane & 3) << 1;
    float sA = (rA < n) ? dis[rA] : 0.f;
    float sB = (rB < n) ? dis[rB] : 0.f;

    #pragma unroll
    for (int j = 0; j < 8; j++) {
        int col = j * 8 + cb;
        if (mode == 0) {
            if (rA < n)
                *(float2*)&Y[rA * 64 + col] = make_float2(c[j][0] * sA, c[j][1] * sA);
            if (rB < n)
                *(float2*)&Y[rB * 64 + col] = make_float2(c[j][2] * sB, c[j][3] * sB);
        } else {
            if (rA < n) {
                float h0 = fmaxf(c[j][0] * sA, 0.f) * sA;
                float h1 = fmaxf(c[j][1] * sA, 0.f) * sA;
                *(float2*)&Y[rA * 64 + col] = make_float2(h0, h1);
                *(float2*)&A2[rA * 64 + col] =
                    loops ? make_float2(h0, h1) : make_float2(0.f, 0.f);
            }
            if (rB < n) {
                float h2 = fmaxf(c[j][2] * sB, 0.f) * sB;
                float h3 = fmaxf(c[j][3] * sB, 0.f) * sB;
                *(float2*)&Y[rB * 64 + col] = make_float2(h2, h3);
                *(float2*)&A2[rB * 64 + col] =
                    loops ? make_float2(h2, h3) : make_float2(0.f, 0.f);
            }
        }
    }
}

// ---------------------------------------------------------------------------
// Launch
// ---------------------------------------------------------------------------
extern "C" void kernel_launch(void* const* d_in, const int* in_sizes, int n_in,
                              void* d_out, int out_size)
{
    const float* x   = (const float*)d_in[0];
    const void*  ei  = d_in[1];
    const float* dis = (const float*)d_in[2];
    const float* W1  = (const float*)d_in[n_in - 2];
    const float* W2  = (const float*)d_in[n_in - 1];

    int N = in_sizes[0] / D;
    int E = in_sizes[1] / 2;

    float* xs   = nullptr;
    float* agg  = nullptr;
    float* agg2 = nullptr;
    cudaGetSymbolAddress((void**)&xs,   g_xs);
    cudaGetSymbolAddress((void**)&agg,  g_agg);
    cudaGetSymbolAddress((void**)&agg2, g_agg2);

    int n4    = N * (D / 4);
    int pgrid = (n4 + 255) / 256;
    int sgrid = (E * 16 + 255) / 256;
    int mgrid = (N + 127) / 128;

    detect_kernel<<<1, 1024>>>(ei, E, N);

    // Layer 1
    prescale_kernel<<<pgrid, 256>>>((const float4*)x, dis,
                                    (float4*)xs, (float4*)agg, n4);
    scatter_kernel<<<sgrid, 256>>>((const float4*)xs, ei, agg, E);
    gemm64_kernel<<<mgrid, 256>>>(agg, W1, dis, xs, agg2, N, 1);  // xs := hs

    // Layer 2
    scatter_kernel<<<sgrid, 256>>>((const float4*)xs, ei, agg2, E);
    gemm64_kernel<<<mgrid, 256>>>(agg2, W2, dis, (float*)d_out, nullptr, N, 0);
}

// round 13
// speedup vs baseline: 1.2446x; 1.0164x over previous
#include <cuda_runtime.h>
#include <cuda_fp16.h>
#include <cstdint>

// GCN 2-layer: out = spmm(relu(spmm(X)@W1))@W2,  A_norm = D^-1/2 A D^-1/2
// N=50000, E=850000 (last N edges self-loops, runtime-verified), D=64.
//
// R13 = R12 (HMMA gemm, 118.8us) + fp16 gather features for scatter:
//   - xs/hs stored fp16; scatter: 16 thr/edge, LDG.64 gather (8B), ONE
//     red.global.add.v4.f32 per thread (RED count unchanged vs fp32 version;
//     R6's regression was the doubled RED count, not fp16 itself)
//   - gather LTS bytes/layer: 218MB -> 109MB (predict scatter 38 -> ~30us)
//   - gemm1 epilogue emits hs as fp16 directly
// Accumulation fp32 throughout (REDs into fp32 agg).

#define D 64
#define NMAX 50176

__device__ __half g_xs[NMAX * D];   // prescaled features fp16 (xs, then hs)
__device__ float  g_agg[NMAX * D];  // layer-1 aggregation (fp32)
__device__ float  g_agg2[NMAX * D]; // layer-2 aggregation (fp32)
__device__ int g_is64;
__device__ int g_loops;
__device__ int g_E2;

// ---------------------------------------------------------------------------
// helpers
// ---------------------------------------------------------------------------
__device__ __forceinline__ unsigned h2u(float a, float b) {
    __half2 h = __floats2half2_rn(a, b);
    union { __half2 h; unsigned u; } c;
    c.h = h;
    return c.u;
}
__device__ __forceinline__ __half2 u2h(unsigned u) {
    union { unsigned u; __half2 h; } c;
    c.u = u;
    return c.h;
}
__device__ __forceinline__ void ldmatrix_x4(unsigned* r, unsigned addr) {
    asm volatile("ldmatrix.sync.aligned.m8n8.x4.shared.b16 {%0,%1,%2,%3}, [%4];"
                 : "=r"(r[0]), "=r"(r[1]), "=r"(r[2]), "=r"(r[3]) : "r"(addr));
}
__device__ __forceinline__ void ldmatrix_x4_t(unsigned* r, unsigned addr) {
    asm volatile("ldmatrix.sync.aligned.m8n8.x4.trans.shared.b16 {%0,%1,%2,%3}, [%4];"
                 : "=r"(r[0]), "=r"(r[1]), "=r"(r[2]), "=r"(r[3]) : "r"(addr));
}
__device__ __forceinline__ void mma16816(float* c, const unsigned* a,
                                         unsigned b0, unsigned b1) {
    asm volatile(
        "mma.sync.aligned.m16n8k16.row.col.f32.f16.f16.f32 "
        "{%0,%1,%2,%3}, {%4,%5,%6,%7}, {%8,%9}, {%0,%1,%2,%3};"
        : "+f"(c[0]), "+f"(c[1]), "+f"(c[2]), "+f"(c[3])
        : "r"(a[0]), "r"(a[1]), "r"(a[2]), "r"(a[3]), "r"(b0), "r"(b1));
}

// ---------------------------------------------------------------------------
// Detection: edge dtype + trailing-self-loop structure.
// ---------------------------------------------------------------------------
__global__ void __launch_bounds__(1024) detect_kernel(const void* __restrict__ ei,
                                                      int E, int N) {
    __shared__ int s_is64;
    __shared__ int s_ok;
    int t = threadIdx.x;
    if (t == 0) {
        const int* w = (const int*)ei;
        int is64 = 1;
        #pragma unroll 1
        for (int i = 0; i < 64; i++)
            if (w[2 * i + 1] != 0) { is64 = 0; break; }
        s_is64 = is64;
        s_ok = (E >= N) ? 1 : 0;
    }
    __syncthreads();
    int is64 = s_is64;
    if (E >= N) {
        long long pos = (long long)t * N / 1024;
        long long eidx = (long long)(E - N) + pos;
        long long s, d;
        if (is64) {
            const long long* p = (const long long*)ei;
            s = p[eidx]; d = p[E + eidx];
        } else {
            const int* p = (const int*)ei;
            s = p[eidx]; d = p[E + eidx];
        }
        if (s != pos || d != pos) s_ok = 0;
    }
    __syncthreads();
    if (t == 0) {
        g_is64 = is64;
        g_loops = s_ok;
        g_E2 = s_ok ? (E - N) : E;
    }
}

// ---------------------------------------------------------------------------
// Fused prescale + layer1 init:
//   xs16[i,:] = (half)(dis[i] * x[i,:]) ;  agg1[i,:] = loops ? dis*x : 0 (fp32)
// One thread per 8 elements.
// ---------------------------------------------------------------------------
__global__ void __launch_bounds__(256) prescale_kernel(
    const float4* __restrict__ x, const float* __restrict__ dis,
    uint4* __restrict__ xs, float4* __restrict__ agg, int n8)
{
    int i = blockIdx.x * 256 + threadIdx.x;
    if (i >= n8) return;
    float s = dis[i >> 3];
    float4 a = x[i * 2];
    float4 b = x[i * 2 + 1];
    a.x *= s; a.y *= s; a.z *= s; a.w *= s;
    b.x *= s; b.y *= s; b.z *= s; b.w *= s;
    uint4 o;
    o.x = h2u(a.x, a.y); o.y = h2u(a.z, a.w);
    o.z = h2u(b.x, b.y); o.w = h2u(b.z, b.w);
    xs[i] = o;
    if (g_loops) {
        agg[i * 2]     = a;
        agg[i * 2 + 1] = b;
    } else {
        float4 z = make_float4(0.f, 0.f, 0.f, 0.f);
        agg[i * 2]     = z;
        agg[i * 2 + 1] = z;
    }
}

// ---------------------------------------------------------------------------
// Scatter SPMM: out[dst] += (float)feat16[src]
// 16 threads/edge; each LDG.64 (4 halves), one red.global.add.v4.f32.
// ---------------------------------------------------------------------------
__global__ void __launch_bounds__(256) scatter_kernel(
    const uint2* __restrict__ feat,    // [N,16] uint2 view of [N,64] half
    const void*  __restrict__ ei,
    float*       __restrict__ out,
    int E)
{
    int idx = blockIdx.x * 256 + threadIdx.x;
    int e = idx >> 4;
    if (e >= g_E2) return;
    int lane = idx & 15;

    int s, d;
    if (g_is64) {
        const long long* p = (const long long*)ei;
        s = (int)p[e];
        d = (int)p[E + e];
    } else {
        const int* p = (const int*)ei;
        s = p[e];
        d = p[E + e];
    }

    uint2 v = feat[s * 16 + lane];
    float2 f0 = __half22float2(u2h(v.x));
    float2 f1 = __half22float2(u2h(v.y));

    float* o = out + d * 64 + lane * 4;
    asm volatile("red.global.add.v4.f32 [%0], {%1, %2, %3, %4};"
                 :: "l"(o), "f"(f0.x), "f"(f0.y), "f"(f1.x), "f"(f1.y)
                 : "memory");
}

// ---------------------------------------------------------------------------
// Tensor-core GEMM: t = dis[r] * (X[r,:] @ W),  W 64x64, X fp32 in gmem.
//   mode 0: Yf = t (fp32)
//   mode 1: h = relu(t)*dis[r]; Yh = (half)h; A2 = (loops ? h : 0) (fp32)
// 256 thr (8 warps x 16 rows = 128 rows/CTA), fp16 smem staging + m16n8k16.
// ---------------------------------------------------------------------------
__global__ void __launch_bounds__(256) gemm64_kernel(
    const float* __restrict__ X,
    const float* __restrict__ W,
    const float* __restrict__ dis,
    float*       __restrict__ Yf,
    __half*      __restrict__ Yh,
    float*       __restrict__ A2,
    int n, int mode)
{
    __shared__ __align__(16) __half Wh[64 * 64];    // [k][n], 128B rows
    __shared__ __align__(16) __half Xh[128 * 64];   // [row][k], 128B rows

    int t = threadIdx.x;
    int rbase = blockIdx.x * 128;

    // ---- stage W (fp32 -> fp16, swizzled) ----
    {
        int row = t >> 2, q = t & 3;
        const float4* W4 = (const float4*)W;
        float4 f0 = W4[row * 16 + q * 4 + 0];
        float4 f1 = W4[row * 16 + q * 4 + 1];
        float4 f2 = W4[row * 16 + q * 4 + 2];
        float4 f3 = W4[row * 16 + q * 4 + 3];
        uint4 u0, u1;
        u0.x = h2u(f0.x, f0.y); u0.y = h2u(f0.z, f0.w);
        u0.z = h2u(f1.x, f1.y); u0.w = h2u(f1.z, f1.w);
        u1.x = h2u(f2.x, f2.y); u1.y = h2u(f2.z, f2.w);
        u1.z = h2u(f3.x, f3.y); u1.w = h2u(f3.z, f3.w);
        unsigned sw = (row & 7) << 4;
        char* base = (char*)Wh;
        *(uint4*)(base + ((row * 128 + q * 32     ) ^ sw)) = u0;
        *(uint4*)(base + ((row * 128 + q * 32 + 16) ^ sw)) = u1;
    }

    // ---- stage X tile (fp32 -> fp16, swizzled) ----
    {
        int row = t >> 1, h = t & 1;
        int gr = rbase + row;
        const float4* X4 = (const float4*)X;
        unsigned sw = (row & 7) << 4;
        char* base = (char*)Xh;
        #pragma unroll
        for (int c = 0; c < 4; c++) {
            float4 fa, fb;
            if (gr < n) {
                fa = X4[gr * 16 + h * 8 + c * 2 + 0];
                fb = X4[gr * 16 + h * 8 + c * 2 + 1];
            } else {
                fa = make_float4(0.f, 0.f, 0.f, 0.f);
                fb = fa;
            }
            uint4 u;
            u.x = h2u(fa.x, fa.y); u.y = h2u(fa.z, fa.w);
            u.z = h2u(fb.x, fb.y); u.w = h2u(fb.z, fb.w);
            *(uint4*)(base + ((row * 128 + (h * 4 + c) * 16) ^ sw)) = u;
        }
    }
    __syncthreads();

    int lane = t & 31, wid = t >> 5;
    int r0 = wid << 4;

    unsigned xbase = (unsigned)__cvta_generic_to_shared(Xh);
    unsigned wbase = (unsigned)__cvta_generic_to_shared(Wh);

    // ---- A fragments ----
    unsigned a[4][4];
    {
        int row = r0 + (lane & 7) + (lane & 8);
        unsigned sw = (row & 7) << 4;
        #pragma unroll
        for (int kk = 0; kk < 4; kk++) {
            int chunk = kk * 2 + (lane >> 4);
            unsigned addr = xbase + ((row * 128 + chunk * 16) ^ sw);
            ldmatrix_x4(a[kk], addr);
        }
    }

    float c[8][4];
    #pragma unroll
    for (int j = 0; j < 8; j++)
        #pragma unroll
        for (int q = 0; q < 4; q++)
            c[j][q] = 0.f;

    #pragma unroll
    for (int j = 0; j < 8; j++) {
        unsigned b[8];
        {
            int k0 = lane;
            unsigned addr0 = wbase + ((k0 * 128 + j * 16) ^ ((k0 & 7) << 4));
            ldmatrix_x4_t(b + 0, addr0);
            int k1 = 32 + lane;
            unsigned addr1 = wbase + ((k1 * 128 + j * 16) ^ ((k1 & 7) << 4));
            ldmatrix_x4_t(b + 4, addr1);
        }
        mma16816(c[j], a[0], b[0], b[1]);
        mma16816(c[j], a[1], b[2], b[3]);
        mma16816(c[j], a[2], b[4], b[5]);
        mma16816(c[j], a[3], b[6], b[7]);
    }

    // ---- epilogue ----
    int loops = (mode == 1) ? g_loops : 0;
    int rA = rbase + r0 + (lane >> 2);
    int rB = rA + 8;
    int cb = (lane & 3) << 1;
    float sA = (rA < n) ? dis[rA] : 0.f;
    float sB = (rB < n) ? dis[rB] : 0.f;

    #pragma unroll
    for (int j = 0; j < 8; j++) {
        int col = j * 8 + cb;
        if (mode == 0) {
            if (rA < n)
                *(float2*)&Yf[rA * 64 + col] = make_float2(c[j][0] * sA, c[j][1] * sA);
            if (rB < n)
                *(float2*)&Yf[rB * 64 + col] = make_float2(c[j][2] * sB, c[j][3] * sB);
        } else {
            if (rA < n) {
                float h0 = fmaxf(c[j][0] * sA, 0.f) * sA;
                float h1 = fmaxf(c[j][1] * sA, 0.f) * sA;
                *(__half2*)&Yh[rA * 64 + col] = __floats2half2_rn(h0, h1);
                *(float2*)&A2[rA * 64 + col] =
                    loops ? make_float2(h0, h1) : make_float2(0.f, 0.f);
            }
            if (rB < n) {
                float h2 = fmaxf(c[j][2] * sB, 0.f) * sB;
                float h3 = fmaxf(c[j][3] * sB, 0.f) * sB;
                *(__half2*)&Yh[rB * 64 + col] = __floats2half2_rn(h2, h3);
                *(float2*)&A2[rB * 64 + col] =
                    loops ? make_float2(h2, h3) : make_float2(0.f, 0.f);
            }
        }
    }
}

// ---------------------------------------------------------------------------
// Launch
// ---------------------------------------------------------------------------
extern "C" void kernel_launch(void* const* d_in, const int* in_sizes, int n_in,
                              void* d_out, int out_size)
{
    const float* x   = (const float*)d_in[0];
    const void*  ei  = d_in[1];
    const float* dis = (const float*)d_in[2];
    const float* W1  = (const float*)d_in[n_in - 2];
    const float* W2  = (const float*)d_in[n_in - 1];

    int N = in_sizes[0] / D;
    int E = in_sizes[1] / 2;

    __half* xs  = nullptr;
    float* agg  = nullptr;
    float* agg2 = nullptr;
    cudaGetSymbolAddress((void**)&xs,   g_xs);
    cudaGetSymbolAddress((void**)&agg,  g_agg);
    cudaGetSymbolAddress((void**)&agg2, g_agg2);

    int n8    = N * (D / 8);
    int pgrid = (n8 + 255) / 256;
    int sgrid = (E * 16 + 255) / 256;
    int mgrid = (N + 127) / 128;

    detect_kernel<<<1, 1024>>>(ei, E, N);

    // Layer 1
    prescale_kernel<<<pgrid, 256>>>((const float4*)x, dis,
                                    (uint4*)xs, (float4*)agg, n8);
    scatter_kernel<<<sgrid, 256>>>((const uint2*)xs, ei, agg, E);
    gemm64_kernel<<<mgrid, 256>>>(agg, W1, dis, nullptr, xs, agg2, N, 1); // xs := hs16

    // Layer 2
    scatter_kernel<<<sgrid, 256>>>((const uint2*)xs, ei, agg2, E);
    gemm64_kernel<<<mgrid, 256>>>(agg2, W2, dis, (float*)d_out, nullptr, nullptr, N, 0);
}